// round 12
// baseline (speedup 1.0000x reference)
#include <cuda_runtime.h>
#include <math.h>
#include <stdint.h>

#define BDIM 4096
#define DDIM 512
#define NBINS 10
#define TM 128             // block tile rows (A)
#define TN 64              // block tile cols (B)
#define GX 64
#define GY 32
#define NCTA (GX * GY)     // 2048 launched (~1056 live)
#define KC 32              // int8 K-elements per stage (32 B/row)
#define NST (DDIM / KC)    // 16 stages
#define SROWB 48           // padded row stride (32B data + 16B) -> conflict-free
#define AQ1_OFF 0
#define AQ2_OFF (128 * SROWB)          // 6144
#define BQ1_OFF (256 * SROWB)          // 12288
#define BQ2_OFF (320 * SROWB)          // 15360
#define STAGE_B (384 * SROWB)          // 18432
#define NSTAGE 3
#define DYN_SMEM (NSTAGE * STAGE_B)    // 55296

// ---------------------------------------------------------------------------
// device scratch (no allocations allowed)
// ---------------------------------------------------------------------------
__device__ signed char g_q1[BDIM * DDIM];
__device__ signed char g_q2[BDIM * DDIM];
__device__ int   g_tgt[BDIM];
__device__ float g_cntf[NBINS];
__device__ float g_sum[NBINS];
__device__ int   g_ticket;

// ---------------------------------------------------------------------------
// helpers (base-ISA only: cp.async, ldmatrix, mma.sync s8 — compute_103-safe)
// ---------------------------------------------------------------------------
__device__ __forceinline__ uint32_t smem_to_u32(const void* p) {
    uint32_t a;
    asm("{ .reg .u64 t; cvta.to.shared.u64 t, %1; cvt.u32.u64 %0, t; }"
        : "=r"(a) : "l"(p));
    return a;
}
__device__ __forceinline__ void cp16(uint32_t dst, const void* src) {
    asm volatile("cp.async.cg.shared.global [%0], [%1], 16;" :: "r"(dst), "l"(src));
}
#define CP_COMMIT() asm volatile("cp.async.commit_group;" ::: "memory")
#define CP_WAIT(n)  asm volatile("cp.async.wait_group %0;" :: "n"(n) : "memory")

__device__ __forceinline__ void ldsm_x4(uint32_t* r, uint32_t addr) {
    asm volatile("ldmatrix.sync.aligned.m8n8.x4.shared.b16 {%0,%1,%2,%3}, [%4];"
                 : "=r"(r[0]), "=r"(r[1]), "=r"(r[2]), "=r"(r[3]) : "r"(addr));
}
// s8 IMMA m16n8k32, s32 accumulate
__device__ __forceinline__ void imma(int* d, const uint32_t* a, const uint32_t* b) {
    asm volatile("mma.sync.aligned.m16n8k32.row.col.s32.s8.s8.s32 "
                 "{%0,%1,%2,%3}, {%4,%5,%6,%7}, {%8,%9}, {%0,%1,%2,%3};"
                 : "+r"(d[0]), "+r"(d[1]), "+r"(d[2]), "+r"(d[3])
                 : "r"(a[0]), "r"(a[1]), "r"(a[2]), "r"(a[3]),
                   "r"(b[0]), "r"(b[1]));
}

// ---------------------------------------------------------------------------
// Kernel 1: blocks 0..4095 normalize+quantize rows; block 4096 decodes
// targets (sniffs int32 vs int64) and zeros histogram/ticket state.
// 127*xn ~= q1 + q2/128  (q1 in [-127,127], q2 in [-64,64])
// ---------------------------------------------------------------------------
__global__ void prep_kernel(const float* __restrict__ x,
                            const int* __restrict__ tgt_words) {
    int blk = blockIdx.x;
    int tid = threadIdx.x;  // 0..127

    if (blk == BDIM) {
        __shared__ int s_any_odd;
        if (tid == 0) s_any_odd = 0;
        __syncthreads();
        int local = 0;
        #pragma unroll
        for (int r = 0; r < 32; r++) {
            int i = tid + r * 128;
            local |= tgt_words[2 * i + 1];   // odd word under int64 hypothesis
        }
        if (local) atomicOr(&s_any_odd, 1);
        __syncthreads();
        bool is32 = (s_any_odd != 0);
        #pragma unroll
        for (int r = 0; r < 32; r++) {
            int i = tid + r * 128;
            g_tgt[i] = is32 ? tgt_words[i] : tgt_words[2 * i];
        }
        if (tid < NBINS) { g_cntf[tid] = 0.0f; g_sum[tid] = 0.0f; }
        if (tid == 0) g_ticket = 0;
        return;
    }

    float4 v = ((const float4*)(x + (size_t)blk * DDIM))[tid];
    float ss = v.x * v.x + v.y * v.y + v.z * v.z + v.w * v.w;
    #pragma unroll
    for (int o = 16; o > 0; o >>= 1) ss += __shfl_down_sync(0xffffffffu, ss, o);
    __shared__ float ws[4];
    if ((tid & 31) == 0) ws[tid >> 5] = ss;
    __syncthreads();
    float tot = ws[0] + ws[1] + ws[2] + ws[3];
    float inv = 127.0f / fmaxf(sqrtf(tot), 1e-12f);

    float f[4] = {v.x * inv, v.y * inv, v.z * inv, v.w * inv};
    int q1[4], q2[4];
    #pragma unroll
    for (int i = 0; i < 4; i++) {
        float t1 = rintf(f[i]);
        q1[i] = (int)t1;
        q2[i] = (int)rintf((f[i] - t1) * 128.0f);
    }
    size_t base = (size_t)blk * DDIM + tid * 4;
    *(char4*)(g_q1 + base) = make_char4((char)q1[0], (char)q1[1], (char)q1[2], (char)q1[3]);
    *(char4*)(g_q2 + base) = make_char4((char)q2[0], (char)q2[1], (char)q2[2], (char)q2[3]);
}

// ---------------------------------------------------------------------------
// Kernel 2: int8 3-term exact Gram (q1q1 + (q1q2+q2q1)/128), 128x64 tiles,
// 3-stage cp.async ring, fused fast-path histogram, ticket finalize.
// 256 threads = 8 warps (4 row-bands x 2 col-bands), warp tile 32x32.
// ---------------------------------------------------------------------------
__global__ __launch_bounds__(256, 2) void ghm_mma_kernel(
        const float* __restrict__ acc_sum, float* __restrict__ out) {
    int cx = blockIdx.x;        // col block (64 cols)
    int by = blockIdx.y;        // row block (128 rows)
    bool live = (cx >= 2 * by); // upper-triangular blocks only

    __shared__ int   s_tr[TM], s_tc[TN];
    __shared__ float s_cnt[NBINS], s_sum[NBINS];
    __shared__ int   s_last;
    extern __shared__ __align__(16) char dynsmem[];

    int tid = threadIdx.x, wid = tid >> 5, lid = tid & 31;

    if (live) {
        int rowA = by * TM, colB = cx * TN;
        int warp_m = wid & 3;        // 0..3 -> 32-row band
        int warp_n = wid >> 2;       // 0..1 -> 32-col band

        // per-warp symmetric weight (verified in R11)
        float wf;
        if (cx >= 2 * by + 2)      wf = 2.0f;
        else if (cx == 2 * by)     wf = (warp_m < 2) ? 1.0f : 2.0f;
        else                       wf = (warp_m < 2) ? 0.0f : 1.0f;

        if (tid < NBINS) { s_cnt[tid] = 0.0f; s_sum[tid] = 0.0f; }
        if (tid < TM) s_tr[tid] = g_tgt[rowA + tid];
        if (tid < TN) s_tc[tid] = g_tgt[colB + tid];

        uint32_t sb = smem_to_u32(dynsmem);
        uint32_t sbase[NSTAGE] = {sb, sb + STAGE_B, sb + 2 * STAGE_B};

        // cp.async: 3 x 16B chunks per thread per stage
        //   chunk0: A q1 (256 chunks), chunk1: A q2, chunk2: B q1/q2 (128+128)
        int arow = tid >> 1, ac = tid & 1;
        int bsel = tid >> 7;                       // 0 -> B q1, 1 -> B q2
        int brow = (tid & 127) >> 1, bc = tid & 1;
        uint32_t off0 = (uint32_t)(AQ1_OFF + arow * SROWB + ac * 16);
        uint32_t off1 = (uint32_t)(AQ2_OFF + arow * SROWB + ac * 16);
        uint32_t off2 = (uint32_t)(BQ1_OFF + bsel * (BQ2_OFF - BQ1_OFF)
                                   + brow * SROWB + bc * 16);
        const signed char* p0 = g_q1 + (size_t)(rowA + arow) * DDIM + ac * 16;
        const signed char* p1 = g_q2 + (size_t)(rowA + arow) * DDIM + ac * 16;
        const signed char* p2 = (bsel ? g_q2 : g_q1)
                                + (size_t)(colB + brow) * DDIM + bc * 16;

        int acc1[2][4][4], acc2[2][4][4];
        #pragma unroll
        for (int mf = 0; mf < 2; mf++)
            #pragma unroll
            for (int nf = 0; nf < 4; nf++)
                #pragma unroll
                for (int r = 0; r < 4; r++) { acc1[mf][nf][r] = 0; acc2[mf][nf][r] = 0; }

        // ldsm lane addressing (stage-relative)
        // A x4: rows (lid&15), k-half (lid>>4)*16B; q1/q2 via tile offset
        uint32_t a_off = (uint32_t)((warp_m * 32 + (lid & 15)) * SROWB + (lid >> 4) * 16);
        // B x4 fused q1/q2: lanes 0-15 -> Bq1 (k halves), lanes 16-31 -> Bq2
        uint32_t b_off = (uint32_t)(BQ1_OFF +
                         (warp_n * 32 + (lid & 7)) * SROWB +
                         ((lid >> 3) & 1) * 16 +
                         (lid >> 4) * (BQ2_OFF - BQ1_OFF));

        // prologue: issue stages 0, 1
        #pragma unroll
        for (int s = 0; s < 2; s++) {
            uint32_t base = sbase[s];
            cp16(base + off0, p0);
            cp16(base + off1, p1);
            cp16(base + off2, p2);
            CP_COMMIT();
            p0 += KC; p1 += KC; p2 += KC;
        }

        int cb = 0, ib = 2;
        for (int s = 0; s < NST; s++) {
            CP_WAIT(1);
            __syncthreads();

            if (s + 2 < NST) {
                uint32_t base = sbase[ib];
                cp16(base + off0, p0);
                cp16(base + off1, p1);
                cp16(base + off2, p2);
                p0 += KC; p1 += KC; p2 += KC;
            }
            CP_COMMIT();

            uint32_t cur = sbase[cb];
            uint32_t aq1[2][4], aq2[2][4], bf[4][4];
            #pragma unroll
            for (int nf = 0; nf < 4; nf++)
                ldsm_x4(bf[nf], cur + b_off + (uint32_t)(nf * 8 * SROWB));
            #pragma unroll
            for (int mf = 0; mf < 2; mf++) {
                uint32_t ao = a_off + (uint32_t)(mf * 16 * SROWB);
                ldsm_x4(aq1[mf], cur + ao);
                ldsm_x4(aq2[mf], cur + ao + AQ2_OFF);
            }
            // term 1: q1*q1 -> acc1
            #pragma unroll
            for (int mf = 0; mf < 2; mf++)
                #pragma unroll
                for (int nf = 0; nf < 4; nf++)
                    imma(acc1[mf][nf], aq1[mf], &bf[nf][0]);
            // terms 2+3: q1*q2 + q2*q1 -> acc2
            #pragma unroll
            for (int mf = 0; mf < 2; mf++)
                #pragma unroll
                for (int nf = 0; nf < 4; nf++)
                    imma(acc2[mf][nf], aq1[mf], &bf[nf][2]);
            #pragma unroll
            for (int mf = 0; mf < 2; mf++)
                #pragma unroll
                for (int nf = 0; nf < 4; nf++)
                    imma(acc2[mf][nf], aq2[mf], &bf[nf][0]);

            cb = (cb == 2) ? 0 : cb + 1;
            ib = (ib == 2) ? 0 : ib + 1;
        }

        // -------------- epilogue: fast-path histogram --------------
        const float E10 = 1.0f + 1e-6f;
        const float INV = 1.0f / 16129.0f;        // 1/127^2
        if (wf > 0.0f) {
            float b0s = 0.0f, b0c = 0.0f, b1s = 0.0f, b1c = 0.0f;
            #pragma unroll
            for (int mf = 0; mf < 2; mf++) {
                int rr = warp_m * 32 + mf * 16 + (lid >> 2);
                int tr0 = s_tr[rr], tr8 = s_tr[rr + 8];
                #pragma unroll
                for (int nf = 0; nf < 4; nf++) {
                    int cc = warp_n * 32 + nf * 8 + (lid & 3) * 2;
                    int tc0 = s_tc[cc], tc1 = s_tc[cc + 1];
                    int rowt[4] = {tr0, tr0, tr8, tr8};
                    int colt[4] = {tc0, tc1, tc0, tc1};
                    #pragma unroll
                    for (int e = 0; e < 4; e++) {
                        float cosv = (__int2float_rn(acc1[mf][nf][e]) +
                                      __int2float_rn(acc2[mf][nf][e]) * 0.0078125f) * INV;
                        float lab  = (rowt[e] == colt[e]) ? 1.0f : 0.0f;
                        float dv   = lab - cosv;
                        float g    = fabsf(dv);
                        float g2   = dv * dv;
                        if (g < 0.1f)       { b0s += g2; b0c += 1.0f; }
                        else if (g < 0.2f)  { b1s += g2; b1c += 1.0f; }
                        else {
                            int idx = (int)(g * 10.0f);
                            if (idx > 9) idx = (g < E10) ? 9 : 10;
                            if (idx < 10) {
                                atomicAdd(&s_sum[idx], wf * g2);
                                atomicAdd(&s_cnt[idx], wf);
                            }
                        }
                    }
                }
            }
            #pragma unroll
            for (int o = 16; o > 0; o >>= 1) {
                b0s += __shfl_down_sync(0xffffffffu, b0s, o);
                b0c += __shfl_down_sync(0xffffffffu, b0c, o);
                b1s += __shfl_down_sync(0xffffffffu, b1s, o);
                b1c += __shfl_down_sync(0xffffffffu, b1c, o);
            }
            if (lid == 0) {
                atomicAdd(&s_sum[0], wf * b0s);
                atomicAdd(&s_cnt[0], wf * b0c);
                atomicAdd(&s_sum[1], wf * b1s);
                atomicAdd(&s_cnt[1], wf * b1c);
            }
        }
        __syncthreads();
        if (tid < NBINS) {
            atomicAdd(&g_sum[tid], s_cnt[tid] >= 0.0f ? s_sum[tid] : 0.0f);
            atomicAdd(&g_cntf[tid], s_cnt[tid]);
        }
    }

    // ----------------- completion ticket: last CTA finalizes -----------------
    __syncthreads();
    if (tid == 0) {
        __threadfence();
        int done = atomicAdd(&g_ticket, 1);
        s_last = (done == NCTA - 1) ? 1 : 0;
    }
    __syncthreads();
    if (s_last && tid == 0) {
        const float tot = (float)BDIM * (float)BDIM;
        float cts[NBINS], sums[NBINS], vn = 0.0f;
        #pragma unroll
        for (int b = 0; b < NBINS; b++) {
            cts[b]  = atomicAdd(&g_cntf[b], 0.0f);  // L2-coherent read
            sums[b] = atomicAdd(&g_sum[b], 0.0f);
            vn += cts[b];
        }
        float loss = 0.0f;
        #pragma unroll
        for (int b = 0; b < NBINS; b++) {
            float accn = 0.5f * acc_sum[b] + 0.5f * cts[b];  // momentum = 0.5
            float w = tot / (accn + 1e-6f);
            loss += sums[b] * w;
        }
        if (vn > 0.0f) loss /= vn;
        loss /= tot;
        *out = loss;
    }
}

extern "C" void kernel_launch(void* const* d_in, const int* in_sizes, int n_in,
                              void* d_out, int out_size) {
    const float* x       = (const float*)d_in[0];
    const float* acc_sum = (const float*)d_in[1];
    const int*   tgt     = (const int*)d_in[2];   // int32 view; prep sniffs layout
    float*       out     = (float*)d_out;

    cudaFuncSetAttribute(ghm_mma_kernel,
                         cudaFuncAttributeMaxDynamicSharedMemorySize, DYN_SMEM);

    prep_kernel<<<BDIM + 1, 128>>>(x, tgt);
    dim3 grid(GX, GY);
    ghm_mma_kernel<<<grid, 256, DYN_SMEM>>>(acc_sum, out);
}

// round 13
// speedup vs baseline: 3.3733x; 3.3733x over previous
#include <cuda_runtime.h>
#include <cuda_fp16.h>
#include <math.h>
#include <stdint.h>

#define BDIM 4096
#define DDIM 512
#define NBINS 10
#define TILE 128
#define NT   32            // tiles per dimension
#define NTRI 528           // NT*(NT+1)/2 upper-triangular tiles
#define KC   32            // fp16 K-elements per pipeline stage (64 B/row)
#define NST  (DDIM / KC)   // 16 stages
#define SROWB 80           // padded SMEM row stride bytes (64B data + 16B pad)
#define TILE_SMEMB (TILE * SROWB)     // 10240 B per tile
#define STAGE_B (2 * TILE_SMEMB)      // A, B = 20480 B
#define NSTAGE 3
#define DYN_SMEM (NSTAGE * STAGE_B)   // 61440 B

// ---------------------------------------------------------------------------
// device scratch (no allocations allowed)
// ---------------------------------------------------------------------------
__device__ __half g_h[BDIM * DDIM];   // fp16 normalized rows
__device__ int   g_tgt[BDIM];
__device__ float g_cntf[NBINS];
__device__ float g_sum[NBINS];
__device__ int   g_ticket;

// ---------------------------------------------------------------------------
// helpers (base-ISA only: cp.async, ldmatrix, mma.sync — compute_103-safe)
// ---------------------------------------------------------------------------
__device__ __forceinline__ uint32_t smem_to_u32(const void* p) {
    uint32_t a;
    asm("{ .reg .u64 t; cvta.to.shared.u64 t, %1; cvt.u32.u64 %0, t; }"
        : "=r"(a) : "l"(p));
    return a;
}
__device__ __forceinline__ void cp16(uint32_t dst, const void* src) {
    asm volatile("cp.async.cg.shared.global [%0], [%1], 16;" :: "r"(dst), "l"(src));
}
#define CP_COMMIT() asm volatile("cp.async.commit_group;" ::: "memory")
#define CP_WAIT(n)  asm volatile("cp.async.wait_group %0;" :: "n"(n) : "memory")

__device__ __forceinline__ void ldsm_x4(uint32_t* r, uint32_t addr) {
    asm volatile("ldmatrix.sync.aligned.m8n8.x4.shared.b16 {%0,%1,%2,%3}, [%4];"
                 : "=r"(r[0]), "=r"(r[1]), "=r"(r[2]), "=r"(r[3]) : "r"(addr));
}
__device__ __forceinline__ void mma_f16(float* d, const uint32_t* a, const uint32_t* b) {
    asm volatile("mma.sync.aligned.m16n8k16.row.col.f32.f16.f16.f32 "
                 "{%0,%1,%2,%3}, {%4,%5,%6,%7}, {%8,%9}, {%0,%1,%2,%3};"
                 : "+f"(d[0]), "+f"(d[1]), "+f"(d[2]), "+f"(d[3])
                 : "r"(a[0]), "r"(a[1]), "r"(a[2]), "r"(a[3]),
                   "r"(b[0]), "r"(b[1]));
}

// ---------------------------------------------------------------------------
// Kernel 1: blocks 0..4095 normalize rows -> fp16; block 4096 decodes targets
// (sniffs int32 vs int64 storage) and zeros the histogram/ticket state.
// ---------------------------------------------------------------------------
__global__ void prep_kernel(const float* __restrict__ x,
                            const int* __restrict__ tgt_words) {
    int blk = blockIdx.x;
    int tid = threadIdx.x;  // 0..127

    if (blk == BDIM) {
        __shared__ int s_any_odd;
        if (tid == 0) s_any_odd = 0;
        __syncthreads();
        int local = 0;
        #pragma unroll
        for (int r = 0; r < 32; r++) {
            int i = tid + r * 128;
            local |= tgt_words[2 * i + 1];   // odd word under int64 hypothesis
        }
        if (local) atomicOr(&s_any_odd, 1);
        __syncthreads();
        bool is32 = (s_any_odd != 0);
        #pragma unroll
        for (int r = 0; r < 32; r++) {
            int i = tid + r * 128;
            g_tgt[i] = is32 ? tgt_words[i] : tgt_words[2 * i];
        }
        if (tid < NBINS) { g_cntf[tid] = 0.0f; g_sum[tid] = 0.0f; }
        if (tid == 0) g_ticket = 0;
        return;
    }

    float4 v = ((const float4*)(x + (size_t)blk * DDIM))[tid];
    float ss = v.x * v.x + v.y * v.y + v.z * v.z + v.w * v.w;
    #pragma unroll
    for (int o = 16; o > 0; o >>= 1) ss += __shfl_down_sync(0xffffffffu, ss, o);
    __shared__ float ws[4];
    if ((tid & 31) == 0) ws[tid >> 5] = ss;
    __syncthreads();
    float tot = ws[0] + ws[1] + ws[2] + ws[3];
    float inv = 1.0f / fmaxf(sqrtf(tot), 1e-12f);

    size_t base = (size_t)blk * DDIM + tid * 4;
    *(__half2*)(g_h + base)     = __half2(__float2half(v.x * inv), __float2half(v.y * inv));
    *(__half2*)(g_h + base + 2) = __half2(__float2half(v.z * inv), __float2half(v.w * inv));
}

// ---------------------------------------------------------------------------
// Kernel 2: 3-stage ring pipelined plain-fp16 Gram tile + fused histogram +
// inline finalize by last CTA. 256 threads = 8 warps (2x4), warp tile 64x32.
// B ldsm fuses two nf-bands per x4 (lanes 16-31 -> +8 rows).
// ---------------------------------------------------------------------------
__global__ __launch_bounds__(256, 2) void ghm_mma_kernel(
        const float* __restrict__ acc_sum, float* __restrict__ out) {
    // triangular decode: tile t -> (by, bx), bx >= by
    int t = blockIdx.x;
    int by = (int)floorf(32.5f - 0.5f * sqrtf(4225.0f - 8.0f * (float)t));
    if (by < 0) by = 0;
    if (by > NT - 1) by = NT - 1;
    int S = by * NT - (by * (by - 1)) / 2;
    while (S + (NT - by) <= t) { S += NT - by; by++; }
    while (S > t) { by--; S -= NT - by; }
    int bx = by + (t - S);
    int rowA = by * TILE, rowB = bx * TILE;

    extern __shared__ __align__(16) char dynsmem[];
    __shared__ int   s_tr[TILE], s_tc[TILE];
    __shared__ float s_cnt[NBINS], s_sum[NBINS];
    __shared__ int   s_last;

    int tid = threadIdx.x, wid = tid >> 5, lid = tid & 31;
    int warp_m = wid & 1;        // 0..1 -> 64-row band
    int warp_n = wid >> 1;       // 0..3 -> 32-col band

    if (tid < NBINS) { s_cnt[tid] = 0.0f; s_sum[tid] = 0.0f; }
    if (tid < TILE) {
        s_tr[tid] = g_tgt[rowA + tid];
        s_tc[tid] = g_tgt[rowB + tid];
    }

    uint32_t sb = smem_to_u32(dynsmem);
    uint32_t sbase[NSTAGE] = {sb, sb + STAGE_B, sb + 2 * STAGE_B};

    // per-thread cp.async geometry: two 16B chunks per tile per stage
    int r0 = tid >> 2, c0 = tid & 3;                 // chunk 0: rows 0..63
    int roff0 = r0 * DDIM + c0 * 8;                  // element offsets (fp16)
    int roff1 = (r0 + 64) * DDIM + c0 * 8;           // chunk 1: rows 64..127
    uint32_t doff0 = (uint32_t)(r0 * SROWB + c0 * 16);
    uint32_t doff1 = (uint32_t)((r0 + 64) * SROWB + c0 * 16);

    // mutable source pointers, advanced KC elements per issued stage
    const __half* pA = g_h + (size_t)rowA * DDIM;
    const __half* pB = g_h + (size_t)rowB * DDIM;

    float acc[4][4][4];
    #pragma unroll
    for (int mf = 0; mf < 4; mf++)
        #pragma unroll
        for (int nf = 0; nf < 4; nf++)
            #pragma unroll
            for (int r = 0; r < 4; r++) acc[mf][nf][r] = 0.0f;

    // ldmatrix lane addressing (stage-relative):
    // A x4: rows (lid&15), k-chunk (lid>>4)
    uint32_t a_off = (uint32_t)((warp_m * 64 + (lid & 15)) * SROWB + (lid >> 4) * 16);
    // B x4 fused nf-pair: lanes 0-15 -> band 2p (rows lid&7, k-chunk (lid>>3)&1),
    //                     lanes 16-31 -> band 2p+1 (+8 rows)
    uint32_t b_off = (uint32_t)(TILE_SMEMB +                       // B tile base
                     (warp_n * 32 + (lid & 7)) * SROWB +
                     ((lid >> 3) & 1) * 16 +
                     (lid >> 4) * (8 * SROWB));

    // prologue: issue stages 0, 1
    #pragma unroll
    for (int s = 0; s < 2; s++) {
        uint32_t base = sbase[s];
        cp16(base + doff0,              pA + roff0);
        cp16(base + doff1,              pA + roff1);
        cp16(base + TILE_SMEMB + doff0, pB + roff0);
        cp16(base + TILE_SMEMB + doff1, pB + roff1);
        CP_COMMIT();
        pA += KC; pB += KC;
    }

    int cb = 0;      // compute buffer (kb % 3)
    int ib = 2;      // issue buffer  ((kb+2) % 3)
    for (int kb = 0; kb < NST; kb++) {
        CP_WAIT(1);          // own stage-kb group complete
        __syncthreads();     // all warps done reading buffer ib (stage kb-1)

        if (kb + 2 < NST) {  // issue stage kb+2 into buffer ib
            uint32_t base = sbase[ib];
            cp16(base + doff0,              pA + roff0);
            cp16(base + doff1,              pA + roff1);
            cp16(base + TILE_SMEMB + doff0, pB + roff0);
            cp16(base + TILE_SMEMB + doff1, pB + roff1);
            pA += KC; pB += KC;
        }
        CP_COMMIT();         // empty group in tail keeps accounting exact

        uint32_t cur = sbase[cb];
        #pragma unroll
        for (int ks = 0; ks < 2; ks++) {
            uint32_t kcol = (uint32_t)(ks * 32);
            uint32_t bf[2][4];   // nf pair p: [0..1]=band 2p, [2..3]=band 2p+1
            #pragma unroll
            for (int p = 0; p < 2; p++)
                ldsm_x4(bf[p], cur + b_off + (uint32_t)(p * 16 * SROWB) + kcol);
            #pragma unroll
            for (int mf = 0; mf < 4; mf++) {
                uint32_t ah[4];
                ldsm_x4(ah, cur + a_off + (uint32_t)(mf * 16 * SROWB) + kcol);
                #pragma unroll
                for (int nf = 0; nf < 4; nf++)
                    mma_f16(acc[mf][nf], ah, &bf[nf >> 1][(nf & 1) * 2]);
            }
        }
        cb = (cb == 2) ? 0 : cb + 1;
        ib = (ib == 2) ? 0 : ib + 1;
    }

    // ------------------- epilogue: bin accumulators -------------------
    const float E10 = 1.0f + 1e-6f;           // last edge (fp32, as reference)
    float wf = (bx == by) ? 1.0f : 2.0f;      // off-diag tiles: (i,j) and (j,i)

    float bsum[NBINS], bcnt[NBINS];
    #pragma unroll
    for (int b = 0; b < NBINS; b++) { bsum[b] = 0.0f; bcnt[b] = 0.0f; }

    #pragma unroll
    for (int mf = 0; mf < 4; mf++) {
        int rr = warp_m * 64 + mf * 16 + (lid >> 2);
        int tr0 = s_tr[rr], tr8 = s_tr[rr + 8];
        #pragma unroll
        for (int nf = 0; nf < 4; nf++) {
            int cc = warp_n * 32 + nf * 8 + (lid & 3) * 2;
            int tc0 = s_tc[cc], tc1 = s_tc[cc + 1];
            int rowt[4] = {tr0, tr0, tr8, tr8};
            int colt[4] = {tc0, tc1, tc0, tc1};
            #pragma unroll
            for (int e = 0; e < 4; e++) {
                float cosv = acc[mf][nf][e];
                float lab  = (rowt[e] == colt[e]) ? 1.0f : 0.0f;
                float dv   = lab - cosv;
                float g    = fabsf(dv);
                int idx = (int)(g * 10.0f);            // fast binning
                idx = (idx > 9) ? ((g < E10) ? 9 : 10) : idx;  // [1.0,1+1e-6)->bin9
                float g2 = dv * dv;
                #pragma unroll
                for (int b = 0; b < NBINS; b++) {
                    bool hit = (idx == b);
                    bsum[b] += hit ? g2 : 0.0f;
                    bcnt[b] += hit ? 1.0f : 0.0f;
                }
            }
        }
    }

    #pragma unroll
    for (int b = 0; b < NBINS; b++) {
        #pragma unroll
        for (int o = 16; o > 0; o >>= 1) {
            bsum[b] += __shfl_down_sync(0xffffffffu, bsum[b], o);
            bcnt[b] += __shfl_down_sync(0xffffffffu, bcnt[b], o);
        }
    }
    if (lid == 0) {
        #pragma unroll
        for (int b = 0; b < NBINS; b++) {
            atomicAdd(&s_sum[b], wf * bsum[b]);
            atomicAdd(&s_cnt[b], wf * bcnt[b]);
        }
    }
    __syncthreads();
    if (tid < NBINS) {
        atomicAdd(&g_sum[tid], s_sum[tid]);
        atomicAdd(&g_cntf[tid], s_cnt[tid]);
    }

    // ----------------- completion ticket: last CTA finalizes -----------------
    __syncthreads();
    if (tid == 0) {
        __threadfence();
        int done = atomicAdd(&g_ticket, 1);
        s_last = (done == NTRI - 1) ? 1 : 0;
    }
    __syncthreads();
    if (s_last && tid == 0) {
        const float tot = (float)BDIM * (float)BDIM;
        float cts[NBINS], sums[NBINS], vn = 0.0f;
        #pragma unroll
        for (int b = 0; b < NBINS; b++) {
            cts[b]  = atomicAdd(&g_cntf[b], 0.0f);  // L2-coherent read
            sums[b] = atomicAdd(&g_sum[b], 0.0f);
            vn += cts[b];
        }
        float loss = 0.0f;
        #pragma unroll
        for (int b = 0; b < NBINS; b++) {
            float accn = 0.5f * acc_sum[b] + 0.5f * cts[b];  // momentum = 0.5
            float w = tot / (accn + 1e-6f);
            loss += sums[b] * w;
        }
        if (vn > 0.0f) loss /= vn;
        loss /= tot;
        *out = loss;
    }
}

extern "C" void kernel_launch(void* const* d_in, const int* in_sizes, int n_in,
                              void* d_out, int out_size) {
    const float* x       = (const float*)d_in[0];
    const float* acc_sum = (const float*)d_in[1];
    const int*   tgt     = (const int*)d_in[2];   // int32 view; prep sniffs layout
    float*       out     = (float*)d_out;

    cudaFuncSetAttribute(ghm_mma_kernel,
                         cudaFuncAttributeMaxDynamicSharedMemorySize, DYN_SMEM);

    prep_kernel<<<BDIM + 1, 128>>>(x, tgt);
    ghm_mma_kernel<<<NTRI, 256, DYN_SMEM>>>(acc_sum, out);
}

// round 14
// speedup vs baseline: 3.7263x; 1.1046x over previous
#include <cuda_runtime.h>
#include <cuda_fp16.h>
#include <math.h>
#include <stdint.h>

#define BDIM 4096
#define DDIM 512
#define NBINS 10
#define TILE 128
#define NT   32            // tiles per dimension
#define NTRI 528           // NT*(NT+1)/2 upper-triangular tiles
#define KC   32            // fp16 K-elements per pipeline stage (64 B/row)
#define NST  (DDIM / KC)   // 16 stages
#define SROWB 80           // padded SMEM row stride bytes (64B data + 16B pad)
#define TILE_SMEMB (TILE * SROWB)     // 10240 B per tile
#define STAGE_B (2 * TILE_SMEMB)      // A, B = 20480 B
#define NSTAGE 3
#define DYN_SMEM (NSTAGE * STAGE_B)   // 61440 B

// ---------------------------------------------------------------------------
// device scratch (no allocations allowed)
// ---------------------------------------------------------------------------
__device__ __half g_h[BDIM * DDIM];   // fp16 normalized rows
__device__ int   g_tgt[BDIM];
__device__ float g_cntf[NBINS];
__device__ float g_sum[NBINS];
__device__ int   g_ticket;

// ---------------------------------------------------------------------------
// helpers (base-ISA only: cp.async, ldmatrix, mma.sync — compute_103-safe)
// ---------------------------------------------------------------------------
__device__ __forceinline__ uint32_t smem_to_u32(const void* p) {
    uint32_t a;
    asm("{ .reg .u64 t; cvta.to.shared.u64 t, %1; cvt.u32.u64 %0, t; }"
        : "=r"(a) : "l"(p));
    return a;
}
__device__ __forceinline__ void cp16(uint32_t dst, const void* src) {
    asm volatile("cp.async.cg.shared.global [%0], [%1], 16;" :: "r"(dst), "l"(src));
}
#define CP_COMMIT() asm volatile("cp.async.commit_group;" ::: "memory")
#define CP_WAIT(n)  asm volatile("cp.async.wait_group %0;" :: "n"(n) : "memory")

__device__ __forceinline__ void ldsm_x4(uint32_t* r, uint32_t addr) {
    asm volatile("ldmatrix.sync.aligned.m8n8.x4.shared.b16 {%0,%1,%2,%3}, [%4];"
                 : "=r"(r[0]), "=r"(r[1]), "=r"(r[2]), "=r"(r[3]) : "r"(addr));
}
__device__ __forceinline__ void mma_f16(float* d, const uint32_t* a, const uint32_t* b) {
    asm volatile("mma.sync.aligned.m16n8k16.row.col.f32.f16.f16.f32 "
                 "{%0,%1,%2,%3}, {%4,%5,%6,%7}, {%8,%9}, {%0,%1,%2,%3};"
                 : "+f"(d[0]), "+f"(d[1]), "+f"(d[2]), "+f"(d[3])
                 : "r"(a[0]), "r"(a[1]), "r"(a[2]), "r"(a[3]),
                   "r"(b[0]), "r"(b[1]));
}

// ---------------------------------------------------------------------------
// Kernel 1: blocks 0..4095 normalize rows -> fp16; block 4096 decodes targets
// (sniffs int32 vs int64 storage) and zeros the histogram/ticket state.
// ---------------------------------------------------------------------------
__global__ void prep_kernel(const float* __restrict__ x,
                            const int* __restrict__ tgt_words) {
    int blk = blockIdx.x;
    int tid = threadIdx.x;  // 0..127

    if (blk == BDIM) {
        __shared__ int s_any_odd;
        if (tid == 0) s_any_odd = 0;
        __syncthreads();
        int local = 0;
        #pragma unroll
        for (int r = 0; r < 32; r++) {
            int i = tid + r * 128;
            local |= tgt_words[2 * i + 1];   // odd word under int64 hypothesis
        }
        if (local) atomicOr(&s_any_odd, 1);
        __syncthreads();
        bool is32 = (s_any_odd != 0);
        #pragma unroll
        for (int r = 0; r < 32; r++) {
            int i = tid + r * 128;
            g_tgt[i] = is32 ? tgt_words[i] : tgt_words[2 * i];
        }
        if (tid < NBINS) { g_cntf[tid] = 0.0f; g_sum[tid] = 0.0f; }
        if (tid == 0) g_ticket = 0;
        return;
    }

    float4 v = ((const float4*)(x + (size_t)blk * DDIM))[tid];
    float ss = v.x * v.x + v.y * v.y + v.z * v.z + v.w * v.w;
    #pragma unroll
    for (int o = 16; o > 0; o >>= 1) ss += __shfl_down_sync(0xffffffffu, ss, o);
    __shared__ float ws[4];
    if ((tid & 31) == 0) ws[tid >> 5] = ss;
    __syncthreads();
    float tot = ws[0] + ws[1] + ws[2] + ws[3];
    float inv = 1.0f / fmaxf(sqrtf(tot), 1e-12f);

    size_t base = (size_t)blk * DDIM + tid * 4;
    *(__half2*)(g_h + base)     = __half2(__float2half(v.x * inv), __float2half(v.y * inv));
    *(__half2*)(g_h + base + 2) = __half2(__float2half(v.z * inv), __float2half(v.w * inv));
}

// ---------------------------------------------------------------------------
// Kernel 2: 3-stage ring pipelined plain-fp16 Gram tile + fast-path fused
// histogram (bins 0/1 in regs, rare elements via shared atomics) + ticket
// finalize. 256 threads = 8 warps (2x4), warp tile 64x32.
// ---------------------------------------------------------------------------
__global__ __launch_bounds__(256, 2) void ghm_mma_kernel(
        const float* __restrict__ acc_sum, float* __restrict__ out) {
    // triangular decode: tile t -> (by, bx), bx >= by
    int t = blockIdx.x;
    int by = (int)floorf(32.5f - 0.5f * sqrtf(4225.0f - 8.0f * (float)t));
    if (by < 0) by = 0;
    if (by > NT - 1) by = NT - 1;
    int S = by * NT - (by * (by - 1)) / 2;
    while (S + (NT - by) <= t) { S += NT - by; by++; }
    while (S > t) { by--; S -= NT - by; }
    int bx = by + (t - S);
    int rowA = by * TILE, rowB = bx * TILE;

    extern __shared__ __align__(16) char dynsmem[];
    __shared__ int   s_tr[TILE], s_tc[TILE];
    __shared__ float s_cnt[NBINS], s_sum[NBINS];
    __shared__ int   s_last;

    int tid = threadIdx.x, wid = tid >> 5, lid = tid & 31;
    int warp_m = wid & 1;        // 0..1 -> 64-row band
    int warp_n = wid >> 1;       // 0..3 -> 32-col band

    if (tid < NBINS) { s_cnt[tid] = 0.0f; s_sum[tid] = 0.0f; }
    if (tid < TILE) {
        s_tr[tid] = g_tgt[rowA + tid];
        s_tc[tid] = g_tgt[rowB + tid];
    }

    uint32_t sb = smem_to_u32(dynsmem);
    uint32_t sbase[NSTAGE] = {sb, sb + STAGE_B, sb + 2 * STAGE_B};

    // per-thread cp.async geometry: two 16B chunks per tile per stage
    int r0 = tid >> 2, c0 = tid & 3;                 // chunk 0: rows 0..63
    int roff0 = r0 * DDIM + c0 * 8;                  // element offsets (fp16)
    int roff1 = (r0 + 64) * DDIM + c0 * 8;           // chunk 1: rows 64..127
    uint32_t doff0 = (uint32_t)(r0 * SROWB + c0 * 16);
    uint32_t doff1 = (uint32_t)((r0 + 64) * SROWB + c0 * 16);

    // mutable source pointers, advanced KC elements per issued stage
    const __half* pA = g_h + (size_t)rowA * DDIM;
    const __half* pB = g_h + (size_t)rowB * DDIM;

    float acc[4][4][4];
    #pragma unroll
    for (int mf = 0; mf < 4; mf++)
        #pragma unroll
        for (int nf = 0; nf < 4; nf++)
            #pragma unroll
            for (int r = 0; r < 4; r++) acc[mf][nf][r] = 0.0f;

    // ldmatrix lane addressing (stage-relative):
    // A x4: rows (lid&15), k-chunk (lid>>4)
    uint32_t a_off = (uint32_t)((warp_m * 64 + (lid & 15)) * SROWB + (lid >> 4) * 16);
    // B x4 fused nf-pair: lanes 0-15 -> band 2p, lanes 16-31 -> band 2p+1 (+8 rows)
    uint32_t b_off = (uint32_t)(TILE_SMEMB +
                     (warp_n * 32 + (lid & 7)) * SROWB +
                     ((lid >> 3) & 1) * 16 +
                     (lid >> 4) * (8 * SROWB));

    // prologue: issue stages 0, 1
    #pragma unroll
    for (int s = 0; s < 2; s++) {
        uint32_t base = sbase[s];
        cp16(base + doff0,              pA + roff0);
        cp16(base + doff1,              pA + roff1);
        cp16(base + TILE_SMEMB + doff0, pB + roff0);
        cp16(base + TILE_SMEMB + doff1, pB + roff1);
        CP_COMMIT();
        pA += KC; pB += KC;
    }

    int cb = 0;      // compute buffer (kb % 3)
    int ib = 2;      // issue buffer  ((kb+2) % 3)
    for (int kb = 0; kb < NST; kb++) {
        CP_WAIT(1);          // own stage-kb group complete
        __syncthreads();     // all warps done reading buffer ib (stage kb-1)

        if (kb + 2 < NST) {  // issue stage kb+2 into buffer ib
            uint32_t base = sbase[ib];
            cp16(base + doff0,              pA + roff0);
            cp16(base + doff1,              pA + roff1);
            cp16(base + TILE_SMEMB + doff0, pB + roff0);
            cp16(base + TILE_SMEMB + doff1, pB + roff1);
            pA += KC; pB += KC;
        }
        CP_COMMIT();         // empty group in tail keeps accounting exact

        uint32_t cur = sbase[cb];
        #pragma unroll
        for (int ks = 0; ks < 2; ks++) {
            uint32_t kcol = (uint32_t)(ks * 32);
            uint32_t bf[2][4];   // nf pair p: [0..1]=band 2p, [2..3]=band 2p+1
            #pragma unroll
            for (int p = 0; p < 2; p++)
                ldsm_x4(bf[p], cur + b_off + (uint32_t)(p * 16 * SROWB) + kcol);
            #pragma unroll
            for (int mf = 0; mf < 4; mf++) {
                uint32_t ah[4];
                ldsm_x4(ah, cur + a_off + (uint32_t)(mf * 16 * SROWB) + kcol);
                #pragma unroll
                for (int nf = 0; nf < 4; nf++)
                    mma_f16(acc[mf][nf], ah, &bf[nf >> 1][(nf & 1) * 2]);
            }
        }
        cb = (cb == 2) ? 0 : cb + 1;
        ib = (ib == 2) ? 0 : ib + 1;
    }

    // --------- epilogue: fast-path histogram (bins 0/1 in registers) ---------
    const float E10 = 1.0f + 1e-6f;           // last edge (fp32, as reference)
    float wf = (bx == by) ? 1.0f : 2.0f;      // off-diag tiles: (i,j) and (j,i)

    float b0s = 0.0f, b0c = 0.0f, b1s = 0.0f, b1c = 0.0f;

    #pragma unroll
    for (int mf = 0; mf < 4; mf++) {
        int rr = warp_m * 64 + mf * 16 + (lid >> 2);
        int tr0 = s_tr[rr], tr8 = s_tr[rr + 8];
        #pragma unroll
        for (int nf = 0; nf < 4; nf++) {
            int cc = warp_n * 32 + nf * 8 + (lid & 3) * 2;
            int tc0 = s_tc[cc], tc1 = s_tc[cc + 1];
            int rowt[4] = {tr0, tr0, tr8, tr8};
            int colt[4] = {tc0, tc1, tc0, tc1};
            #pragma unroll
            for (int e = 0; e < 4; e++) {
                float cosv = acc[mf][nf][e];
                float lab  = (rowt[e] == colt[e]) ? 1.0f : 0.0f;
                float dv   = lab - cosv;
                float g    = fabsf(dv);
                float g2   = dv * dv;
                if (g < 0.1f)       { b0s += g2; b0c += 1.0f; }
                else if (g < 0.2f)  { b1s += g2; b1c += 1.0f; }
                else {
                    int idx = (int)(g * 10.0f);
                    if (idx > 9) idx = (g < E10) ? 9 : 10;
                    if (idx < 10) {
                        atomicAdd(&s_sum[idx], wf * g2);
                        atomicAdd(&s_cnt[idx], wf);
                    }
                }
            }
        }
    }

    #pragma unroll
    for (int o = 16; o > 0; o >>= 1) {
        b0s += __shfl_down_sync(0xffffffffu, b0s, o);
        b0c += __shfl_down_sync(0xffffffffu, b0c, o);
        b1s += __shfl_down_sync(0xffffffffu, b1s, o);
        b1c += __shfl_down_sync(0xffffffffu, b1c, o);
    }
    if (lid == 0) {
        atomicAdd(&s_sum[0], wf * b0s);
        atomicAdd(&s_cnt[0], wf * b0c);
        atomicAdd(&s_sum[1], wf * b1s);
        atomicAdd(&s_cnt[1], wf * b1c);
    }
    __syncthreads();
    if (tid < NBINS) {
        atomicAdd(&g_sum[tid], s_sum[tid]);
        atomicAdd(&g_cntf[tid], s_cnt[tid]);
    }

    // ----------------- completion ticket: last CTA finalizes -----------------
    __syncthreads();
    if (tid == 0) {
        __threadfence();
        int done = atomicAdd(&g_ticket, 1);
        s_last = (done == NTRI - 1) ? 1 : 0;
    }
    __syncthreads();
    if (s_last && tid == 0) {
        const float tot = (float)BDIM * (float)BDIM;
        float cts[NBINS], sums[NBINS], vn = 0.0f;
        #pragma unroll
        for (int b = 0; b < NBINS; b++) {
            cts[b]  = atomicAdd(&g_cntf[b], 0.0f);  // L2-coherent read
            sums[b] = atomicAdd(&g_sum[b], 0.0f);
            vn += cts[b];
        }
        float loss = 0.0f;
        #pragma unroll
        for (int b = 0; b < NBINS; b++) {
            float accn = 0.5f * acc_sum[b] + 0.5f * cts[b];  // momentum = 0.5
            float w = tot / (accn + 1e-6f);
            loss += sums[b] * w;
        }
        if (vn > 0.0f) loss /= vn;
        loss /= tot;
        *out = loss;
    }
}

extern "C" void kernel_launch(void* const* d_in, const int* in_sizes, int n_in,
                              void* d_out, int out_size) {
    const float* x       = (const float*)d_in[0];
    const float* acc_sum = (const float*)d_in[1];
    const int*   tgt     = (const int*)d_in[2];   // int32 view; prep sniffs layout
    float*       out     = (float*)d_out;

    cudaFuncSetAttribute(ghm_mma_kernel,
                         cudaFuncAttributeMaxDynamicSharedMemorySize, DYN_SMEM);

    prep_kernel<<<BDIM + 1, 128>>>(x, tgt);
    ghm_mma_kernel<<<NTRI, 256, DYN_SMEM>>>(acc_sum, out);
}